// round 1
// baseline (speedup 1.0000x reference)
#include <cuda_runtime.h>
#include <math.h>

#define BATCH 2
#define TSEQ  2048
#define EDIM  1024
#define NHEAD 16
#define DHEAD 64
#define MTOT  (BATCH*TSEQ)   // 4096

// Scratch (static device globals: allocation-free, graph-safe)
static __device__ float g_qkv[(size_t)3 * NHEAD * MTOT * DHEAD]; // [z][h][m][d], 48 MB
static __device__ float g_att[(size_t)MTOT * EDIM];              // [m][h*D+d],  16 MB

// ---------------------------------------------------------------------------
// QKV projection: C_z[h][m][d] = sum_e x[m][e] * W_z[h][e][d]
// Classic 128x128x16 register-tiled SGEMM; B indexed through [h][e][d] weights.
// ---------------------------------------------------------------------------
__global__ __launch_bounds__(256) void qkv_gemm(
    const float* __restrict__ x,
    const float* __restrict__ Wq,
    const float* __restrict__ Wk,
    const float* __restrict__ Wv)
{
    constexpr int BM = 128, BN = 128, BK = 16;
    __shared__ float As[BK][BM + 4];
    __shared__ float Bs[BK][BN + 4];

    const float* W = (blockIdx.z == 0) ? Wq : ((blockIdx.z == 1) ? Wk : Wv);
    float* C = g_qkv + (size_t)blockIdx.z * NHEAD * MTOT * DHEAD;

    const int m0 = blockIdx.y * BM;
    const int n0 = blockIdx.x * BN;
    const int tid = threadIdx.x;
    const int ty = tid >> 4, tx = tid & 15;

    const int ar = tid >> 1, ac = (tid & 1) * 8;   // A loader: 128 rows x 16 k
    const int br = tid >> 4, bc = (tid & 15) * 8;  // B loader: 16 k x 128 n

    float acc[8][8];
#pragma unroll
    for (int i = 0; i < 8; i++)
#pragma unroll
        for (int j = 0; j < 8; j++) acc[i][j] = 0.f;

    const int nb = n0 + bc;
    const float* bp_base = W + (size_t)(nb >> 6) * EDIM * DHEAD + (nb & 63);

    for (int k0 = 0; k0 < EDIM; k0 += BK) {
        const float* ap = x + (size_t)(m0 + ar) * EDIM + k0 + ac;
        float4 a0 = *(const float4*)(ap);
        float4 a1 = *(const float4*)(ap + 4);
        As[ac + 0][ar] = a0.x; As[ac + 1][ar] = a0.y;
        As[ac + 2][ar] = a0.z; As[ac + 3][ar] = a0.w;
        As[ac + 4][ar] = a1.x; As[ac + 5][ar] = a1.y;
        As[ac + 6][ar] = a1.z; As[ac + 7][ar] = a1.w;

        const float* bp = bp_base + (size_t)(k0 + br) * DHEAD;
        *(float4*)&Bs[br][bc]     = *(const float4*)(bp);
        *(float4*)&Bs[br][bc + 4] = *(const float4*)(bp + 4);
        __syncthreads();

#pragma unroll
        for (int kk = 0; kk < BK; kk++) {
            float af[8], bf[8];
            *(float4*)(af)     = *(const float4*)&As[kk][ty * 4];
            *(float4*)(af + 4) = *(const float4*)&As[kk][ty * 4 + 64];
            *(float4*)(bf)     = *(const float4*)&Bs[kk][tx * 4];
            *(float4*)(bf + 4) = *(const float4*)&Bs[kk][tx * 4 + 64];
#pragma unroll
            for (int i = 0; i < 8; i++)
#pragma unroll
                for (int j = 0; j < 8; j++)
                    acc[i][j] = fmaf(af[i], bf[j], acc[i][j]);
        }
        __syncthreads();
    }

#pragma unroll
    for (int i = 0; i < 8; i++) {
        const int m  = m0 + ty * 4 + (i & 3) + (i >> 2) * 64;
        const int n1 = n0 + tx * 4;
        const int n2 = n1 + 64;
        float* c1 = C + (size_t)(n1 >> 6) * MTOT * DHEAD + (size_t)m * DHEAD + (n1 & 63);
        float* c2 = C + (size_t)(n2 >> 6) * MTOT * DHEAD + (size_t)m * DHEAD + (n2 & 63);
        *(float4*)c1 = make_float4(acc[i][0], acc[i][1], acc[i][2], acc[i][3]);
        *(float4*)c2 = make_float4(acc[i][4], acc[i][5], acc[i][6], acc[i][7]);
    }
}

// ---------------------------------------------------------------------------
// Flash attention (fp32, causal, online softmax), 64x64 tiles, 256 threads.
// Q/K stored d-major with XOR swizzle, V row-major with XOR swizzle.
// P^T aliases the K buffer (extra barrier protects the overlap).
// Writes att in [b*t][(h d)] layout for the output GEMM.
// ---------------------------------------------------------------------------
__global__ __launch_bounds__(256) void flash_attn()
{
    __shared__ float Qs[64 * 64];   // Qs[d*64 + (i ^ ((d>>4&3)<<3))]
    __shared__ float KPs[64 * 64];  // K: [d*64 + (j ^ ((d>>4&3)<<3))]; later P^T: [j*64 + (i ^ ((j>>4&3)<<3))]
    __shared__ float Vs[64 * 64];   // Vs[j*64 + (d ^ ((j&3)<<2))]

    const int h = blockIdx.y >> 1;
    const int b = blockIdx.y & 1;
    const int i0 = (gridDim.x - 1 - blockIdx.x) * 64;  // heavy tiles first

    const float* Qg = g_qkv + ((size_t)h * MTOT + (size_t)b * TSEQ) * DHEAD;
    const float* Kg = Qg + (size_t)NHEAD * MTOT * DHEAD;
    const float* Vg = Kg + (size_t)NHEAD * MTOT * DHEAD;

    const int tid = threadIdx.x;
    const int ty = tid >> 4, tx = tid & 15;
    const int lr = tid >> 2, lc = (tid & 3) * 16;  // loader: row lr, d range [lc,lc+16)

    // Load Q tile transposed + swizzled
    {
        const float* qp = Qg + (size_t)(i0 + lr) * DHEAD + lc;
        float4 v0 = *(const float4*)(qp);
        float4 v1 = *(const float4*)(qp + 4);
        float4 v2 = *(const float4*)(qp + 8);
        float4 v3 = *(const float4*)(qp + 12);
        float tmp[16] = {v0.x,v0.y,v0.z,v0.w, v1.x,v1.y,v1.z,v1.w,
                         v2.x,v2.y,v2.z,v2.w, v3.x,v3.y,v3.z,v3.w};
#pragma unroll
        for (int i = 0; i < 16; i++) {
            const int d = lc + i;
            Qs[d * 64 + (lr ^ (((d >> 4) & 3) << 3))] = tmp[i];
        }
    }

    float m_i[4], l_i[4], o[4][4];
#pragma unroll
    for (int i = 0; i < 4; i++) {
        m_i[i] = -INFINITY; l_i[i] = 0.f;
#pragma unroll
        for (int c = 0; c < 4; c++) o[i][c] = 0.f;
    }

    const float inv_scale = 0.02209708691207961f;  // 1/sqrt(2048)
    const int ntiles = i0 / 64 + 1;

    for (int t = 0; t < ntiles; t++) {
        const int j0 = t * 64;
        __syncthreads();  // previous iteration fully done with KPs/Vs

        // Load K (transposed+swizzled) and V (row-major+swizzled)
        {
            const float* kp = Kg + (size_t)(j0 + lr) * DHEAD + lc;
            float4 v0 = *(const float4*)(kp);
            float4 v1 = *(const float4*)(kp + 4);
            float4 v2 = *(const float4*)(kp + 8);
            float4 v3 = *(const float4*)(kp + 12);
            float tmp[16] = {v0.x,v0.y,v0.z,v0.w, v1.x,v1.y,v1.z,v1.w,
                             v2.x,v2.y,v2.z,v2.w, v3.x,v3.y,v3.z,v3.w};
#pragma unroll
            for (int i = 0; i < 16; i++) {
                const int d = lc + i;
                KPs[d * 64 + (lr ^ (((d >> 4) & 3) << 3))] = tmp[i];
            }
            const float* vp = Vg + (size_t)(j0 + lr) * DHEAD + lc;
            float4 w0 = *(const float4*)(vp);
            float4 w1 = *(const float4*)(vp + 4);
            float4 w2 = *(const float4*)(vp + 8);
            float4 w3 = *(const float4*)(vp + 12);
            const int vsw = (lr & 3) << 2;
            *(float4*)&Vs[lr * 64 + ((lc +  0) ^ vsw)] = w0;
            *(float4*)&Vs[lr * 64 + ((lc +  4) ^ vsw)] = w1;
            *(float4*)&Vs[lr * 64 + ((lc +  8) ^ vsw)] = w2;
            *(float4*)&Vs[lr * 64 + ((lc + 12) ^ vsw)] = w3;
        }
        __syncthreads();

        // S = Q K^T (tile), 4x4 micro-tile per thread
        float s[4][4];
#pragma unroll
        for (int i = 0; i < 4; i++)
#pragma unroll
            for (int j = 0; j < 4; j++) s[i][j] = 0.f;

#pragma unroll
        for (int dg = 0; dg < 4; dg++) {
            const int sw = dg << 3;
#pragma unroll
            for (int dl = 0; dl < 16; dl++) {
                const int d = dg * 16 + dl;
                float qf[4], kf[4];
                *(float4*)qf = *(const float4*)&Qs[d * 64 + ((ty * 4) ^ sw)];
                *(float4*)kf = *(const float4*)&KPs[d * 64 + ((tx * 4) ^ sw)];
#pragma unroll
                for (int i = 0; i < 4; i++)
#pragma unroll
                    for (int j = 0; j < 4; j++)
                        s[i][j] = fmaf(qf[i], kf[j], s[i][j]);
            }
        }

#pragma unroll
        for (int i = 0; i < 4; i++)
#pragma unroll
            for (int j = 0; j < 4; j++) s[i][j] *= inv_scale;

        if (j0 == i0) {  // diagonal tile: causal mask (col > row -> -inf)
#pragma unroll
            for (int i = 0; i < 4; i++)
#pragma unroll
                for (int j = 0; j < 4; j++)
                    if (tx * 4 + j > ty * 4 + i) s[i][j] = -INFINITY;
        }

        // Online softmax update (row groups span 16 lanes: tx dimension)
#pragma unroll
        for (int i = 0; i < 4; i++) {
            float mloc = fmaxf(fmaxf(s[i][0], s[i][1]), fmaxf(s[i][2], s[i][3]));
            mloc = fmaxf(mloc, __shfl_xor_sync(0xffffffffu, mloc, 1));
            mloc = fmaxf(mloc, __shfl_xor_sync(0xffffffffu, mloc, 2));
            mloc = fmaxf(mloc, __shfl_xor_sync(0xffffffffu, mloc, 4));
            mloc = fmaxf(mloc, __shfl_xor_sync(0xffffffffu, mloc, 8));
            const float mnew = fmaxf(m_i[i], mloc);
            const float corr = expf(m_i[i] - mnew);
            float p0 = expf(s[i][0] - mnew);
            float p1 = expf(s[i][1] - mnew);
            float p2 = expf(s[i][2] - mnew);
            float p3 = expf(s[i][3] - mnew);
            float lloc = (p0 + p1) + (p2 + p3);
            lloc += __shfl_xor_sync(0xffffffffu, lloc, 1);
            lloc += __shfl_xor_sync(0xffffffffu, lloc, 2);
            lloc += __shfl_xor_sync(0xffffffffu, lloc, 4);
            lloc += __shfl_xor_sync(0xffffffffu, lloc, 8);
            l_i[i] = l_i[i] * corr + lloc;
            m_i[i] = mnew;
            o[i][0] *= corr; o[i][1] *= corr; o[i][2] *= corr; o[i][3] *= corr;
            s[i][0] = p0; s[i][1] = p1; s[i][2] = p2; s[i][3] = p3;
        }

        __syncthreads();  // everyone done reading K before P^T overwrites KPs

        // Write P^T into KPs: element (j, i) at [j*64 + (i ^ ((j>>4&3)<<3))]
#pragma unroll
        for (int j = 0; j < 4; j++) {
            const int jj = tx * 4 + j;
            const int sw = ((jj >> 4) & 3) << 3;
#pragma unroll
            for (int i = 0; i < 4; i++)
                KPs[jj * 64 + ((ty * 4 + i) ^ sw)] = s[i][j];
        }
        __syncthreads();

        // O += P V
#pragma unroll
        for (int jg = 0; jg < 4; jg++) {
            const int swp = jg << 3;
#pragma unroll
            for (int jl = 0; jl < 16; jl++) {
                const int j = jg * 16 + jl;
                float pf[4], vf[4];
                *(float4*)pf = *(const float4*)&KPs[j * 64 + ((ty * 4) ^ swp)];
                *(float4*)vf = *(const float4*)&Vs[j * 64 + ((tx * 4) ^ ((jl & 3) << 2))];
#pragma unroll
                for (int i = 0; i < 4; i++)
#pragma unroll
                    for (int c = 0; c < 4; c++)
                        o[i][c] = fmaf(pf[i], vf[c], o[i][c]);
            }
        }
    }

    // Epilogue: normalize and write att[b*T+t][h*D + d]
#pragma unroll
    for (int i = 0; i < 4; i++) {
        const float inv_l = 1.0f / l_i[i];
        const int row = i0 + ty * 4 + i;
        float* op = g_att + (size_t)(b * TSEQ + row) * EDIM + h * DHEAD + tx * 4;
        *(float4*)op = make_float4(o[i][0] * inv_l, o[i][1] * inv_l,
                                   o[i][2] * inv_l, o[i][3] * inv_l);
    }
}

// ---------------------------------------------------------------------------
// Output projection: out[m][n] = sum_k att[m][k] * Wo[n][k]
// ---------------------------------------------------------------------------
__global__ __launch_bounds__(256) void out_gemm(
    const float* __restrict__ Wo, float* __restrict__ out)
{
    constexpr int BM = 128, BN = 128, BK = 16;
    __shared__ float As[BK][BM + 4];
    __shared__ float Bs[BK][BN + 4];

    const int m0 = blockIdx.y * BM;
    const int n0 = blockIdx.x * BN;
    const int tid = threadIdx.x;
    const int ty = tid >> 4, tx = tid & 15;

    const int ar = tid >> 1, ac = (tid & 1) * 8;
    const int bn = tid >> 1, bk = (tid & 1) * 8;

    float acc[8][8];
#pragma unroll
    for (int i = 0; i < 8; i++)
#pragma unroll
        for (int j = 0; j < 8; j++) acc[i][j] = 0.f;

    for (int k0 = 0; k0 < EDIM; k0 += BK) {
        const float* ap = g_att + (size_t)(m0 + ar) * EDIM + k0 + ac;
        float4 a0 = *(const float4*)(ap);
        float4 a1 = *(const float4*)(ap + 4);
        As[ac + 0][ar] = a0.x; As[ac + 1][ar] = a0.y;
        As[ac + 2][ar] = a0.z; As[ac + 3][ar] = a0.w;
        As[ac + 4][ar] = a1.x; As[ac + 5][ar] = a1.y;
        As[ac + 6][ar] = a1.z; As[ac + 7][ar] = a1.w;

        const float* bp = Wo + (size_t)(n0 + bn) * EDIM + k0 + bk;
        float4 b0 = *(const float4*)(bp);
        float4 b1 = *(const float4*)(bp + 4);
        Bs[bk + 0][bn] = b0.x; Bs[bk + 1][bn] = b0.y;
        Bs[bk + 2][bn] = b0.z; Bs[bk + 3][bn] = b0.w;
        Bs[bk + 4][bn] = b1.x; Bs[bk + 5][bn] = b1.y;
        Bs[bk + 6][bn] = b1.z; Bs[bk + 7][bn] = b1.w;
        __syncthreads();

#pragma unroll
        for (int kk = 0; kk < BK; kk++) {
            float af[8], bf[8];
            *(float4*)(af)     = *(const float4*)&As[kk][ty * 4];
            *(float4*)(af + 4) = *(const float4*)&As[kk][ty * 4 + 64];
            *(float4*)(bf)     = *(const float4*)&Bs[kk][tx * 4];
            *(float4*)(bf + 4) = *(const float4*)&Bs[kk][tx * 4 + 64];
#pragma unroll
            for (int i = 0; i < 8; i++)
#pragma unroll
                for (int j = 0; j < 8; j++)
                    acc[i][j] = fmaf(af[i], bf[j], acc[i][j]);
        }
        __syncthreads();
    }

#pragma unroll
    for (int i = 0; i < 8; i++) {
        const int m = m0 + ty * 4 + (i & 3) + (i >> 2) * 64;
        float* c1 = out + (size_t)m * EDIM + n0 + tx * 4;
        *(float4*)c1        = make_float4(acc[i][0], acc[i][1], acc[i][2], acc[i][3]);
        *(float4*)(c1 + 64) = make_float4(acc[i][4], acc[i][5], acc[i][6], acc[i][7]);
    }
}

// ---------------------------------------------------------------------------
extern "C" void kernel_launch(void* const* d_in, const int* in_sizes, int n_in,
                              void* d_out, int out_size)
{
    const float* x  = (const float*)d_in[0];
    // d_in[1] is the boolean mask; it encodes strict-upper-triangular causal,
    // which we implement analytically.
    const float* Wq = (const float*)d_in[2];
    const float* Wk = (const float*)d_in[3];
    const float* Wv = (const float*)d_in[4];
    const float* Wo = (const float*)d_in[5];
    float* out = (float*)d_out;

    dim3 g1(EDIM / 128, MTOT / 128, 3);
    qkv_gemm<<<g1, 256>>>(x, Wq, Wk, Wv);

    dim3 g2(TSEQ / 64, NHEAD * BATCH);
    flash_attn<<<g2, 256>>>();

    dim3 g3(EDIM / 128, MTOT / 128);
    out_gemm<<<g3, 256>>>(Wo, out);
}

// round 3
// speedup vs baseline: 1.3382x; 1.3382x over previous
#include <cuda_runtime.h>
#include <cuda_bf16.h>
#include <math.h>
#include <stdint.h>

#define BATCH 2
#define TSEQ  2048
#define EDIM  1024
#define NHEAD 16
#define DHEAD 64
#define MTOT  (BATCH*TSEQ)   // 4096

// ---------------------------------------------------------------------------
// Scratch (static device globals: allocation-free, graph-safe)
// ---------------------------------------------------------------------------
static __device__ float          g_qkv[(size_t)3 * NHEAD * MTOT * DHEAD]; // [z][h][m][d] fp32
static __device__ __nv_bfloat16  g_xhi[(size_t)MTOT * EDIM];
static __device__ __nv_bfloat16  g_xlo[(size_t)MTOT * EDIM];
static __device__ __nv_bfloat16  g_wthi[(size_t)3 * EDIM * EDIM];   // [z][n=h*64+d][e]
static __device__ __nv_bfloat16  g_wtlo[(size_t)3 * EDIM * EDIM];
static __device__ __nv_bfloat16  g_wohi[(size_t)EDIM * EDIM];       // [n][k]
static __device__ __nv_bfloat16  g_wolo[(size_t)EDIM * EDIM];
static __device__ __nv_bfloat16  g_athi[(size_t)MTOT * EDIM];       // [m][h*64+d]
static __device__ __nv_bfloat16  g_atlo[(size_t)MTOT * EDIM];

// ---------------------------------------------------------------------------
// Portable (sm_100 base) tensor-core helpers: mma.sync + ldmatrix + cp.async
// ---------------------------------------------------------------------------
__device__ __forceinline__ uint32_t smem_u32(const void* p) {
    uint32_t a;
    asm("{ .reg .u64 t; cvta.to.shared.u64 t, %1; cvt.u32.u64 %0, t; }" : "=r"(a) : "l"(p));
    return a;
}
#define CP_ASYNC16(saddr, gptr) \
    asm volatile("cp.async.cg.shared.global [%0], [%1], 16;" :: "r"(saddr), "l"(gptr))
#define CP_COMMIT() asm volatile("cp.async.commit_group;" ::: "memory")
#define CP_WAIT0()  asm volatile("cp.async.wait_group 0;" ::: "memory")

#define LDSM_X4(r0, r1, r2, r3, addr) \
    asm volatile("ldmatrix.sync.aligned.m8n8.x4.shared.b16 {%0,%1,%2,%3}, [%4];" \
                 : "=r"(r0), "=r"(r1), "=r"(r2), "=r"(r3) : "r"(addr))

#define MMA16816(d, a, b0, b1) \
    asm volatile("mma.sync.aligned.m16n8k16.row.col.f32.bf16.bf16.f32 " \
                 "{%0,%1,%2,%3}, {%4,%5,%6,%7}, {%8,%9}, {%0,%1,%2,%3};" \
                 : "+f"((d)[0]), "+f"((d)[1]), "+f"((d)[2]), "+f"((d)[3]) \
                 : "r"((a)[0]), "r"((a)[1]), "r"((a)[2]), "r"((a)[3]), "r"(b0), "r"(b1))

__device__ __forceinline__ uint32_t swz(uint32_t off) {
    return off ^ ((off >> 3) & 0x70);
}

// ---------------------------------------------------------------------------
// Conversion kernels: fp32 -> bf16 hi/lo
// ---------------------------------------------------------------------------
__global__ void conv_elem(const float* __restrict__ src, int mode)
{
    __nv_bfloat16* hi = (mode == 0) ? g_xhi : g_wohi;
    __nv_bfloat16* lo = (mode == 0) ? g_xlo : g_wolo;
    const int i4 = blockIdx.x * blockDim.x + threadIdx.x;
    float4 v = *(const float4*)(src + (size_t)i4 * 4);
    __nv_bfloat16 h0 = __float2bfloat16(v.x), h1 = __float2bfloat16(v.y);
    __nv_bfloat16 h2 = __float2bfloat16(v.z), h3 = __float2bfloat16(v.w);
    *(__nv_bfloat162*)(hi + (size_t)i4 * 4)     = __nv_bfloat162(h0, h1);
    *(__nv_bfloat162*)(hi + (size_t)i4 * 4 + 2) = __nv_bfloat162(h2, h3);
    *(__nv_bfloat162*)(lo + (size_t)i4 * 4) = __nv_bfloat162(
        __float2bfloat16(v.x - __bfloat162float(h0)),
        __float2bfloat16(v.y - __bfloat162float(h1)));
    *(__nv_bfloat162*)(lo + (size_t)i4 * 4 + 2) = __nv_bfloat162(
        __float2bfloat16(v.z - __bfloat162float(h2)),
        __float2bfloat16(v.w - __bfloat162float(h3)));
}

// W[z][h][e][d] -> Wt[z][n=h*64+d][e] hi/lo
__global__ void conv_w(const float* __restrict__ Wq,
                       const float* __restrict__ Wk,
                       const float* __restrict__ Wv)
{
    const int t = blockIdx.x * blockDim.x + threadIdx.x;  // < 1024*1024
    const int n = t >> 10, e = t & 1023;
    const int z = blockIdx.y;
    const float* W = (z == 0) ? Wq : ((z == 1) ? Wk : Wv);
    float v = W[(size_t)(n >> 6) * EDIM * DHEAD + (size_t)e * DHEAD + (n & 63)];
    __nv_bfloat16 h = __float2bfloat16(v);
    g_wthi[(size_t)z * EDIM * EDIM + t] = h;
    g_wtlo[(size_t)z * EDIM * EDIM + t] = __float2bfloat16(v - __bfloat162float(h));
}

// ---------------------------------------------------------------------------
// bf16x3 mma.sync GEMM: C[4096, 1024] = A(hi+lo) * B(hi+lo)^T
// CTA 128x128, BK=64, 8 warps (4x2), warp tile 32x64, 2-stage cp.async.
// mode 0: A=x, B=Wt[z], C=g_qkv [z][h][m][d].  mode 1: A=att, B=Wo, C=out.
// ---------------------------------------------------------------------------
#define MMSTAGE 65536  // per-stage smem bytes: 4 arrays x 128 rows x 128B

__global__ __launch_bounds__(256) void mm128(float* __restrict__ Cout, int mode)
{
    extern __shared__ char smem[];
    const uint32_t sb = smem_u32(smem);
    const int tid = threadIdx.x;
    const int wid = tid >> 5, lane = tid & 31;
    const int z = blockIdx.z;
    const int m0 = blockIdx.y * 128;
    const int n0 = blockIdx.x * 128;

    const __nv_bfloat16* Ah = (mode == 0) ? g_xhi : g_athi;
    const __nv_bfloat16* Al = (mode == 0) ? g_xlo : g_atlo;
    const __nv_bfloat16* Bh = (mode == 0) ? (g_wthi + (size_t)z * EDIM * EDIM) : g_wohi;
    const __nv_bfloat16* Bl = (mode == 0) ? (g_wtlo + (size_t)z * EDIM * EDIM) : g_wolo;
    float* C = (mode == 0) ? (g_qkv + (size_t)z * NHEAD * MTOT * DHEAD) : Cout;

    // loader mapping: thread -> (row r, 32-col half)
    const int r  = tid >> 1;
    const int cb = (tid & 1) * 32;
    const size_t ga_row = (size_t)(m0 + r) * EDIM;
    const size_t gb_row = (size_t)(n0 + r) * EDIM;

    auto load_stage = [&](int s, int k0) {
        const uint32_t base = sb + (uint32_t)s * MMSTAGE;
#pragma unroll
        for (int q = 0; q < 4; q++) {
            const int c = cb + q * 8;
            const uint32_t sw = swz((uint32_t)r * 128u + (uint32_t)c * 2u);
            CP_ASYNC16(base + sw,           Ah + ga_row + k0 + c);
            CP_ASYNC16(base + 16384 + sw,   Al + ga_row + k0 + c);
            CP_ASYNC16(base + 32768 + sw,   Bh + gb_row + k0 + c);
            CP_ASYNC16(base + 49152 + sw,   Bl + gb_row + k0 + c);
        }
        CP_COMMIT();
    };

    const int wm = wid >> 1;           // 0..3 -> M offset wm*32
    const int wn = wid & 1;            // 0..1 -> N offset wn*64
    const int lrow = lane & 15;        // ldmatrix row within 16-row tile
    const int lkh  = lane >> 4;        // 0/1 -> k-half (8 cols)

    float d[2][8][4];
#pragma unroll
    for (int i = 0; i < 2; i++)
#pragma unroll
        for (int j = 0; j < 8; j++)
#pragma unroll
            for (int c = 0; c < 4; c++) d[i][j][c] = 0.f;

    load_stage(0, 0);

#pragma unroll 1
    for (int kb = 0; kb < 16; kb++) {
        const int cur = kb & 1;
        CP_WAIT0();
        __syncthreads();
        if (kb < 15) load_stage(cur ^ 1, (kb + 1) * 64);

        const uint32_t st = sb + (uint32_t)cur * MMSTAGE;
#pragma unroll
        for (int ks = 0; ks < 4; ks++) {
            const int k0 = ks * 16;
            const uint32_t kcol = (uint32_t)(k0 + lkh * 8) * 2u;

            uint32_t ah[2][4], al[2][4];
#pragma unroll
            for (int i = 0; i < 2; i++) {
                const uint32_t off = swz((uint32_t)(wm * 32 + i * 16 + lrow) * 128u + kcol);
                LDSM_X4(ah[i][0], ah[i][1], ah[i][2], ah[i][3], st + off);
                LDSM_X4(al[i][0], al[i][1], al[i][2], al[i][3], st + 16384 + off);
            }
            uint32_t bh[4][4], bl[4][4];
#pragma unroll
            for (int j = 0; j < 4; j++) {
                const uint32_t off = swz((uint32_t)(wn * 64 + j * 16 + lrow) * 128u + kcol);
                LDSM_X4(bh[j][0], bh[j][1], bh[j][2], bh[j][3], st + 32768 + off);
                LDSM_X4(bl[j][0], bl[j][1], bl[j][2], bl[j][3], st + 49152 + off);
            }
#pragma unroll
            for (int i = 0; i < 2; i++) {
#pragma unroll
                for (int j = 0; j < 4; j++) {
                    // n-tile 2j   : b regs {r0, r2};  n-tile 2j+1 : {r1, r3}
                    MMA16816(d[i][2*j],   ah[i], bh[j][0], bh[j][2]);
                    MMA16816(d[i][2*j],   ah[i], bl[j][0], bl[j][2]);
                    MMA16816(d[i][2*j],   al[i], bh[j][0], bh[j][2]);
                    MMA16816(d[i][2*j+1], ah[i], bh[j][1], bh[j][3]);
                    MMA16816(d[i][2*j+1], ah[i], bl[j][1], bl[j][3]);
                    MMA16816(d[i][2*j+1], al[i], bh[j][1], bh[j][3]);
                }
            }
        }
        __syncthreads();
    }

    // Epilogue: C fragment (row = lane/4 [+8], col = (lane%4)*2)
    const int qrow = lane >> 2, qcol = (lane & 3) * 2;
#pragma unroll
    for (int i = 0; i < 2; i++) {
#pragma unroll
        for (int j = 0; j < 8; j++) {
            const int n = n0 + wn * 64 + j * 8 + qcol;
            const int m1 = m0 + wm * 32 + i * 16 + qrow;
#pragma unroll
            for (int hh = 0; hh < 2; hh++) {
                const int m = m1 + hh * 8;
                float* dst;
                if (mode == 0)
                    dst = C + (size_t)(n >> 6) * (MTOT * DHEAD) + (size_t)m * DHEAD + (n & 63);
                else
                    dst = C + (size_t)m * EDIM + n;
                dst[0] = d[i][j][hh * 2 + 0];
                dst[1] = d[i][j][hh * 2 + 1];
            }
        }
    }
}

// ---------------------------------------------------------------------------
// Flash attention (fp32, causal, online softmax), 64x64 tiles, 256 threads.
// Epilogue writes att as bf16 hi/lo.
// ---------------------------------------------------------------------------
__global__ __launch_bounds__(256) void flash_attn()
{
    __shared__ float Qs[64 * 64];
    __shared__ float KPs[64 * 64];
    __shared__ float Vs[64 * 64];

    const int h = blockIdx.y >> 1;
    const int b = blockIdx.y & 1;
    const int i0 = (gridDim.x - 1 - blockIdx.x) * 64;

    const float* Qg = g_qkv + ((size_t)h * MTOT + (size_t)b * TSEQ) * DHEAD;
    const float* Kg = Qg + (size_t)NHEAD * MTOT * DHEAD;
    const float* Vg = Kg + (size_t)NHEAD * MTOT * DHEAD;

    const int tid = threadIdx.x;
    const int ty = tid >> 4, tx = tid & 15;
    const int lr = tid >> 2, lc = (tid & 3) * 16;

    {
        const float* qp = Qg + (size_t)(i0 + lr) * DHEAD + lc;
        float4 v0 = *(const float4*)(qp);
        float4 v1 = *(const float4*)(qp + 4);
        float4 v2 = *(const float4*)(qp + 8);
        float4 v3 = *(const float4*)(qp + 12);
        float tmp[16] = {v0.x,v0.y,v0.z,v0.w, v1.x,v1.y,v1.z,v1.w,
                         v2.x,v2.y,v2.z,v2.w, v3.x,v3.y,v3.z,v3.w};
#pragma unroll
        for (int i = 0; i < 16; i++) {
            const int d = lc + i;
            Qs[d * 64 + (lr ^ (((d >> 4) & 3) << 3))] = tmp[i];
        }
    }

    float m_i[4], l_i[4], o[4][4];
#pragma unroll
    for (int i = 0; i < 4; i++) {
        m_i[i] = -INFINITY; l_i[i] = 0.f;
#pragma unroll
        for (int c = 0; c < 4; c++) o[i][c] = 0.f;
    }

    const float inv_scale = 0.02209708691207961f;  // 1/sqrt(2048)
    const int ntiles = i0 / 64 + 1;

    for (int t = 0; t < ntiles; t++) {
        const int j0 = t * 64;
        __syncthreads();

        {
            const float* kp = Kg + (size_t)(j0 + lr) * DHEAD + lc;
            float4 v0 = *(const float4*)(kp);
            float4 v1 = *(const float4*)(kp + 4);
            float4 v2 = *(const float4*)(kp + 8);
            float4 v3 = *(const float4*)(kp + 12);
            float tmp[16] = {v0.x,v0.y,v0.z,v0.w, v1.x,v1.y,v1.z,v1.w,
                             v2.x,v2.y,v2.z,v2.w, v3.x,v3.y,v3.z,v3.w};
#pragma unroll
            for (int i = 0; i < 16; i++) {
                const int d = lc + i;
                KPs[d * 64 + (lr ^ (((d >> 4) & 3) << 3))] = tmp[i];
            }
            const float* vp = Vg + (size_t)(j0 + lr) * DHEAD + lc;
            float4 w0 = *(const float4*)(vp);
            float4 w1 = *(const float4*)(vp + 4);
            float4 w2 = *(const float4*)(vp + 8);
            float4 w3 = *(const float4*)(vp + 12);
            const int vsw = (lr & 3) << 2;
            *(float4*)&Vs[lr * 64 + ((lc +  0) ^ vsw)] = w0;
            *(float4*)&Vs[lr * 64 + ((lc +  4) ^ vsw)] = w1;
            *(float4*)&Vs[lr * 64 + ((lc +  8) ^ vsw)] = w2;
            *(float4*)&Vs[lr * 64 + ((lc + 12) ^ vsw)] = w3;
        }
        __syncthreads();

        float s[4][4];
#pragma unroll
        for (int i = 0; i < 4; i++)
#pragma unroll
            for (int j = 0; j < 4; j++) s[i][j] = 0.f;

#pragma unroll
        for (int dg = 0; dg < 4; dg++) {
            const int sw = dg << 3;
#pragma unroll
            for (int dl = 0; dl < 16; dl++) {
                const int dd = dg * 16 + dl;
                float qf[4], kf[4];
                *(float4*)qf = *(const float4*)&Qs[dd * 64 + ((ty * 4) ^ sw)];
                *(float4*)kf = *(const float4*)&KPs[dd * 64 + ((tx * 4) ^ sw)];
#pragma unroll
                for (int i = 0; i < 4; i++)
#pragma unroll
                    for (int j = 0; j < 4; j++)
                        s[i][j] = fmaf(qf[i], kf[j], s[i][j]);
            }
        }

#pragma unroll
        for (int i = 0; i < 4; i++)
#pragma unroll
            for (int j = 0; j < 4; j++) s[i][j] *= inv_scale;

        if (j0 == i0) {
#pragma unroll
            for (int i = 0; i < 4; i++)
#pragma unroll
                for (int j = 0; j < 4; j++)
                    if (tx * 4 + j > ty * 4 + i) s[i][j] = -INFINITY;
        }

#pragma unroll
        for (int i = 0; i < 4; i++) {
            float mloc = fmaxf(fmaxf(s[i][0], s[i][1]), fmaxf(s[i][2], s[i][3]));
            mloc = fmaxf(mloc, __shfl_xor_sync(0xffffffffu, mloc, 1));
            mloc = fmaxf(mloc, __shfl_xor_sync(0xffffffffu, mloc, 2));
            mloc = fmaxf(mloc, __shfl_xor_sync(0xffffffffu, mloc, 4));
            mloc = fmaxf(mloc, __shfl_xor_sync(0xffffffffu, mloc, 8));
            const float mnew = fmaxf(m_i[i], mloc);
            const float corr = expf(m_i[i] - mnew);
            float p0 = expf(s[i][0] - mnew);
            float p1 = expf(s[i][1] - mnew);
            float p2 = expf(s[i][2] - mnew);
            float p3 = expf(s[i][3] - mnew);
            float lloc = (p0 + p1) + (p2 + p3);
            lloc += __shfl_xor_sync(0xffffffffu, lloc, 1);
            lloc += __shfl_xor_sync(0xffffffffu, lloc, 2);
            lloc += __shfl_xor_sync(0xffffffffu, lloc, 4);
            lloc += __shfl_xor_sync(0xffffffffu, lloc, 8);
            l_i[i] = l_i[i] * corr + lloc;
            m_i[i] = mnew;
            o[i][0] *= corr; o[i][1] *= corr; o[i][2] *= corr; o[i][3] *= corr;
            s[i][0] = p0; s[i][1] = p1; s[i][2] = p2; s[i][3] = p3;
        }

        __syncthreads();

#pragma unroll
        for (int j = 0; j < 4; j++) {
            const int jj = tx * 4 + j;
            const int sw = ((jj >> 4) & 3) << 3;
#pragma unroll
            for (int i = 0; i < 4; i++)
                KPs[jj * 64 + ((ty * 4 + i) ^ sw)] = s[i][j];
        }
        __syncthreads();

#pragma unroll
        for (int jg = 0; jg < 4; jg++) {
            const int swp = jg << 3;
#pragma unroll
            for (int jl = 0; jl < 16; jl++) {
                const int j = jg * 16 + jl;
                float pf[4], vf[4];
                *(float4*)pf = *(const float4*)&KPs[j * 64 + ((ty * 4) ^ swp)];
                *(float4*)vf = *(const float4*)&Vs[j * 64 + ((tx * 4) ^ ((jl & 3) << 2))];
#pragma unroll
                for (int i = 0; i < 4; i++)
#pragma unroll
                    for (int c = 0; c < 4; c++)
                        o[i][c] = fmaf(pf[i], vf[c], o[i][c]);
            }
        }
    }

    // Epilogue: normalize, write att as bf16 hi/lo at [b*T+t][h*64+d]
#pragma unroll
    for (int i = 0; i < 4; i++) {
        const float inv_l = 1.0f / l_i[i];
        const int row = i0 + ty * 4 + i;
        const size_t idx = (size_t)(b * TSEQ + row) * EDIM + h * DHEAD + tx * 4;
        float v0 = o[i][0] * inv_l, v1 = o[i][1] * inv_l;
        float v2 = o[i][2] * inv_l, v3 = o[i][3] * inv_l;
        __nv_bfloat16 h0 = __float2bfloat16(v0), h1 = __float2bfloat16(v1);
        __nv_bfloat16 h2 = __float2bfloat16(v2), h3 = __float2bfloat16(v3);
        *(__nv_bfloat162*)(g_athi + idx)     = __nv_bfloat162(h0, h1);
        *(__nv_bfloat162*)(g_athi + idx + 2) = __nv_bfloat162(h2, h3);
        *(__nv_bfloat162*)(g_atlo + idx) = __nv_bfloat162(
            __float2bfloat16(v0 - __bfloat162float(h0)),
            __float2bfloat16(v1 - __bfloat162float(h1)));
        *(__nv_bfloat162*)(g_atlo + idx + 2) = __nv_bfloat162(
            __float2bfloat16(v2 - __bfloat162float(h2)),
            __float2bfloat16(v3 - __bfloat162float(h3)));
    }
}

// ---------------------------------------------------------------------------
extern "C" void kernel_launch(void* const* d_in, const int* in_sizes, int n_in,
                              void* d_out, int out_size)
{
    const float* x  = (const float*)d_in[0];
    const float* Wq = (const float*)d_in[2];
    const float* Wk = (const float*)d_in[3];
    const float* Wv = (const float*)d_in[4];
    const float* Wo = (const float*)d_in[5];
    float* out = (float*)d_out;

    cudaFuncSetAttribute(mm128, cudaFuncAttributeMaxDynamicSharedMemorySize, 2 * MMSTAGE);

    // 1) fp32 -> bf16 hi/lo conversions
    conv_elem<<<(MTOT * EDIM) / (256 * 4), 256>>>(x, 0);
    conv_elem<<<(EDIM * EDIM) / (256 * 4), 256>>>(Wo, 1);
    {
        dim3 g((EDIM * EDIM) / 256, 3);
        conv_w<<<g, 256>>>(Wq, Wk, Wv);
    }

    // 2) QKV projection: three 4096x1024x1024 bf16x3 tensor GEMMs
    {
        dim3 g(EDIM / 128, MTOT / 128, 3);
        mm128<<<g, 256, 2 * MMSTAGE>>>(nullptr, 0);
    }

    // 3) Flash attention (fp32)
    {
        dim3 g(TSEQ / 64, NHEAD * BATCH);
        flash_attn<<<g, 256>>>();
    }

    // 4) Output projection: 4096x1024x1024 bf16x3 tensor GEMM
    {
        dim3 g(EDIM / 128, MTOT / 128, 1);
        mm128<<<g, 256, 2 * MMSTAGE>>>(out, 1);
    }
}

// round 4
// speedup vs baseline: 2.1616x; 1.6154x over previous
#include <cuda_runtime.h>
#include <cuda_bf16.h>
#include <math.h>
#include <stdint.h>

#define BATCH 2
#define TSEQ  2048
#define EDIM  1024
#define NHEAD 16
#define DHEAD 64
#define MTOT  (BATCH*TSEQ)   // 4096

// ---------------------------------------------------------------------------
// Scratch (static device globals: allocation-free, graph-safe)
// ---------------------------------------------------------------------------
static __device__ __nv_bfloat16  g_xhi[(size_t)MTOT * EDIM];
static __device__ __nv_bfloat16  g_xlo[(size_t)MTOT * EDIM];
static __device__ __nv_bfloat16  g_wthi[(size_t)3 * EDIM * EDIM];   // [z][n=h*64+d][e]
static __device__ __nv_bfloat16  g_wtlo[(size_t)3 * EDIM * EDIM];
static __device__ __nv_bfloat16  g_wohi[(size_t)EDIM * EDIM];       // [n][k]
static __device__ __nv_bfloat16  g_wolo[(size_t)EDIM * EDIM];
static __device__ __nv_bfloat16  g_athi[(size_t)MTOT * EDIM];       // [m][h*64+d]
static __device__ __nv_bfloat16  g_atlo[(size_t)MTOT * EDIM];
// QKV in bf16 hi/lo: [z][h][m=b*T+t][d]
static __device__ __nv_bfloat16  g_pqkvh[(size_t)3 * NHEAD * MTOT * DHEAD];
static __device__ __nv_bfloat16  g_pqkvl[(size_t)3 * NHEAD * MTOT * DHEAD];

// ---------------------------------------------------------------------------
// Portable (sm_100 base) tensor-core helpers: mma.sync + ldmatrix + cp.async
// ---------------------------------------------------------------------------
__device__ __forceinline__ uint32_t smem_u32(const void* p) {
    uint32_t a;
    asm("{ .reg .u64 t; cvta.to.shared.u64 t, %1; cvt.u32.u64 %0, t; }" : "=r"(a) : "l"(p));
    return a;
}
#define CP_ASYNC16(saddr, gptr) \
    asm volatile("cp.async.cg.shared.global [%0], [%1], 16;" :: "r"(saddr), "l"(gptr))
#define CP_COMMIT() asm volatile("cp.async.commit_group;" ::: "memory")
#define CP_WAIT0()  asm volatile("cp.async.wait_group 0;" ::: "memory")

#define LDSM_X4(r0, r1, r2, r3, addr) \
    asm volatile("ldmatrix.sync.aligned.m8n8.x4.shared.b16 {%0,%1,%2,%3}, [%4];" \
                 : "=r"(r0), "=r"(r1), "=r"(r2), "=r"(r3) : "r"(addr))
#define LDSM_X4_T(r0, r1, r2, r3, addr) \
    asm volatile("ldmatrix.sync.aligned.m8n8.x4.trans.shared.b16 {%0,%1,%2,%3}, [%4];" \
                 : "=r"(r0), "=r"(r1), "=r"(r2), "=r"(r3) : "r"(addr))

#define MMA16816(d, a, b0, b1) \
    asm volatile("mma.sync.aligned.m16n8k16.row.col.f32.bf16.bf16.f32 " \
                 "{%0,%1,%2,%3}, {%4,%5,%6,%7}, {%8,%9}, {%0,%1,%2,%3};" \
                 : "+f"((d)[0]), "+f"((d)[1]), "+f"((d)[2]), "+f"((d)[3]) \
                 : "r"((a)[0]), "r"((a)[1]), "r"((a)[2]), "r"((a)[3]), "r"(b0), "r"(b1))

__device__ __forceinline__ uint32_t swz(uint32_t off) {
    return off ^ ((off >> 3) & 0x70);
}
__device__ __forceinline__ float ex2f(float x) {
    float y; asm("ex2.approx.f32 %0, %1;" : "=f"(y) : "f"(x)); return y;
}
// pack two fp32 into bf16x2 hi/lo splits: hi = {bf(v0), bf(v1)}, lo = residuals
__device__ __forceinline__ void split2(float v0, float v1, uint32_t& hi, uint32_t& lo) {
    __nv_bfloat16 h0 = __float2bfloat16(v0), h1 = __float2bfloat16(v1);
    __nv_bfloat162 hp(h0, h1);
    hi = *(const uint32_t*)&hp;
    __nv_bfloat162 lp(__float2bfloat16(v0 - __bfloat162float(h0)),
                      __float2bfloat16(v1 - __bfloat162float(h1)));
    lo = *(const uint32_t*)&lp;
}

// ---------------------------------------------------------------------------
// Conversion kernels: fp32 -> bf16 hi/lo
// ---------------------------------------------------------------------------
__global__ void conv_elem(const float* __restrict__ src, int mode)
{
    __nv_bfloat16* hi = (mode == 0) ? g_xhi : g_wohi;
    __nv_bfloat16* lo = (mode == 0) ? g_xlo : g_wolo;
    const int i4 = blockIdx.x * blockDim.x + threadIdx.x;
    float4 v = *(const float4*)(src + (size_t)i4 * 4);
    uint32_t h0, l0, h1, l1;
    split2(v.x, v.y, h0, l0);
    split2(v.z, v.w, h1, l1);
    *(uint32_t*)(hi + (size_t)i4 * 4)     = h0;
    *(uint32_t*)(hi + (size_t)i4 * 4 + 2) = h1;
    *(uint32_t*)(lo + (size_t)i4 * 4)     = l0;
    *(uint32_t*)(lo + (size_t)i4 * 4 + 2) = l1;
}

// W[z][h][e][d] -> Wt[z][n=h*64+d][e] hi/lo
__global__ void conv_w(const float* __restrict__ Wq,
                       const float* __restrict__ Wk,
                       const float* __restrict__ Wv)
{
    const int t = blockIdx.x * blockDim.x + threadIdx.x;  // < 1024*1024
    const int n = t >> 10, e = t & 1023;
    const int z = blockIdx.y;
    const float* W = (z == 0) ? Wq : ((z == 1) ? Wk : Wv);
    float v = W[(size_t)(n >> 6) * EDIM * DHEAD + (size_t)e * DHEAD + (n & 63)];
    __nv_bfloat16 h = __float2bfloat16(v);
    g_wthi[(size_t)z * EDIM * EDIM + t] = h;
    g_wtlo[(size_t)z * EDIM * EDIM + t] = __float2bfloat16(v - __bfloat162float(h));
}

// ---------------------------------------------------------------------------
// bf16x3 mma.sync GEMM: C[4096, 1024] = A(hi+lo) * B(hi+lo)^T
// CTA 128x128, BK=64, 8 warps (4x2), warp tile 32x64, 2-stage cp.async.
// mode 0: A=x, B=Wt[z], C -> g_pqkvh/l (bf16 hi/lo, [z][h][m][d]).
// mode 1: A=att, B=Wo, C -> out (fp32 row-major).
// ---------------------------------------------------------------------------
#define MMSTAGE 65536  // per-stage smem bytes: 4 arrays x 128 rows x 128B

__global__ __launch_bounds__(256) void mm128(float* __restrict__ Cout, int mode)
{
    extern __shared__ char smem[];
    const uint32_t sb = smem_u32(smem);
    const int tid = threadIdx.x;
    const int wid = tid >> 5, lane = tid & 31;
    const int z = blockIdx.z;
    const int m0 = blockIdx.y * 128;
    const int n0 = blockIdx.x * 128;

    const __nv_bfloat16* Ah = (mode == 0) ? g_xhi : g_athi;
    const __nv_bfloat16* Al = (mode == 0) ? g_xlo : g_atlo;
    const __nv_bfloat16* Bh = (mode == 0) ? (g_wthi + (size_t)z * EDIM * EDIM) : g_wohi;
    const __nv_bfloat16* Bl = (mode == 0) ? (g_wtlo + (size_t)z * EDIM * EDIM) : g_wolo;

    const int r  = tid >> 1;
    const int cb = (tid & 1) * 32;
    const size_t ga_row = (size_t)(m0 + r) * EDIM;
    const size_t gb_row = (size_t)(n0 + r) * EDIM;

    auto load_stage = [&](int s, int k0) {
        const uint32_t base = sb + (uint32_t)s * MMSTAGE;
#pragma unroll
        for (int q = 0; q < 4; q++) {
            const int c = cb + q * 8;
            const uint32_t sw = swz((uint32_t)r * 128u + (uint32_t)c * 2u);
            CP_ASYNC16(base + sw,           Ah + ga_row + k0 + c);
            CP_ASYNC16(base + 16384 + sw,   Al + ga_row + k0 + c);
            CP_ASYNC16(base + 32768 + sw,   Bh + gb_row + k0 + c);
            CP_ASYNC16(base + 49152 + sw,   Bl + gb_row + k0 + c);
        }
        CP_COMMIT();
    };

    const int wm = wid >> 1;
    const int wn = wid & 1;
    const int lrow = lane & 15;
    const int lkh  = lane >> 4;

    float d[2][8][4];
#pragma unroll
    for (int i = 0; i < 2; i++)
#pragma unroll
        for (int j = 0; j < 8; j++)
#pragma unroll
            for (int c = 0; c < 4; c++) d[i][j][c] = 0.f;

    load_stage(0, 0);

#pragma unroll 1
    for (int kb = 0; kb < 16; kb++) {
        const int cur = kb & 1;
        CP_WAIT0();
        __syncthreads();
        if (kb < 15) load_stage(cur ^ 1, (kb + 1) * 64);

        const uint32_t st = sb + (uint32_t)cur * MMSTAGE;
#pragma unroll
        for (int ks = 0; ks < 4; ks++) {
            const uint32_t kcol = (uint32_t)(ks * 16 + lkh * 8) * 2u;
            uint32_t ah[2][4], al[2][4];
#pragma unroll
            for (int i = 0; i < 2; i++) {
                const uint32_t off = swz((uint32_t)(wm * 32 + i * 16 + lrow) * 128u + kcol);
                LDSM_X4(ah[i][0], ah[i][1], ah[i][2], ah[i][3], st + off);
                LDSM_X4(al[i][0], al[i][1], al[i][2], al[i][3], st + 16384 + off);
            }
            uint32_t bh[4][4], bl[4][4];
#pragma unroll
            for (int j = 0; j < 4; j++) {
                const uint32_t off = swz((uint32_t)(wn * 64 + j * 16 + lrow) * 128u + kcol);
                LDSM_X4(bh[j][0], bh[j][1], bh[j][2], bh[j][3], st + 32768 + off);
                LDSM_X4(bl[j][0], bl[j][1], bl[j][2], bl[j][3], st + 49152 + off);
            }
#pragma unroll
            for (int i = 0; i < 2; i++) {
#pragma unroll
                for (int j = 0; j < 4; j++) {
                    MMA16816(d[i][2*j],   ah[i], bh[j][0], bh[j][2]);
                    MMA16816(d[i][2*j],   ah[i], bl[j][0], bl[j][2]);
                    MMA16816(d[i][2*j],   al[i], bh[j][0], bh[j][2]);
                    MMA16816(d[i][2*j+1], ah[i], bh[j][1], bh[j][3]);
                    MMA16816(d[i][2*j+1], ah[i], bl[j][1], bl[j][3]);
                    MMA16816(d[i][2*j+1], al[i], bh[j][1], bh[j][3]);
                }
            }
        }
        __syncthreads();
    }

    const int qrow = lane >> 2, qcol = (lane & 3) * 2;
#pragma unroll
    for (int i = 0; i < 2; i++) {
#pragma unroll
        for (int j = 0; j < 8; j++) {
            const int n = n0 + wn * 64 + j * 8 + qcol;
            const int m1 = m0 + wm * 32 + i * 16 + qrow;
#pragma unroll
            for (int hh = 0; hh < 2; hh++) {
                const int m = m1 + hh * 8;
                const float v0 = d[i][j][hh * 2 + 0];
                const float v1 = d[i][j][hh * 2 + 1];
                if (mode == 0) {
                    const size_t base = (size_t)(n >> 6) * (MTOT * DHEAD)
                                      + (size_t)m * DHEAD + (n & 63);
                    uint32_t hi, lo;
                    split2(v0, v1, hi, lo);
                    *(uint32_t*)(g_pqkvh + (size_t)z * NHEAD * MTOT * DHEAD + base) = hi;
                    *(uint32_t*)(g_pqkvl + (size_t)z * NHEAD * MTOT * DHEAD + base) = lo;
                } else {
                    float* dst = Cout + (size_t)m * EDIM + n;
                    dst[0] = v0; dst[1] = v1;
                }
            }
        }
    }
}

// ---------------------------------------------------------------------------
// Flash attention with bf16x3 mma.sync. CTA: 128 q-rows x one (h,b).
// 8 warps, warp tile M=16 x N=128 (full softmax rows in-warp).
// KV tiles of 128, double-buffered cp.async (160KB smem).
// P fragments feed PV directly from registers; V via ldmatrix.trans.
// ---------------------------------------------------------------------------
#define FA_SMEM (32768 + 2 * 65536)   // Q hi/lo + 2 KV stages

__global__ __launch_bounds__(256) void flash_mma()
{
    extern __shared__ char fsm[];
    const uint32_t sb = smem_u32(fsm);
    const int tid = threadIdx.x;
    const int wid = tid >> 5, lane = tid & 31;
    const int h = blockIdx.y >> 1;
    const int b = blockIdx.y & 1;
    const int i0 = (int)(gridDim.x - 1 - blockIdx.x) * 128;  // heavy tiles first
    const int ntiles = i0 / 128 + 1;

    const size_t hb = ((size_t)h * MTOT + (size_t)b * TSEQ) * DHEAD;
    const __nv_bfloat16* Qh = g_pqkvh + hb;
    const __nv_bfloat16* Ql = g_pqkvl + hb;
    const __nv_bfloat16* Kh = g_pqkvh + (size_t)NHEAD * MTOT * DHEAD + hb;
    const __nv_bfloat16* Kl = g_pqkvl + (size_t)NHEAD * MTOT * DHEAD + hb;
    const __nv_bfloat16* Vh = g_pqkvh + (size_t)2 * NHEAD * MTOT * DHEAD + hb;
    const __nv_bfloat16* Vl = g_pqkvl + (size_t)2 * NHEAD * MTOT * DHEAD + hb;

    const int r  = tid >> 1;
    const int cb = (tid & 1) * 32;

    // Q (one-time) + KV stage 0, one commit group
    {
#pragma unroll
        for (int q = 0; q < 4; q++) {
            const int c = cb + q * 8;
            const uint32_t sw = swz((uint32_t)r * 128u + (uint32_t)c * 2u);
            CP_ASYNC16(sb + sw,          Qh + (size_t)(i0 + r) * DHEAD + c);
            CP_ASYNC16(sb + 16384 + sw,  Ql + (size_t)(i0 + r) * DHEAD + c);
        }
    }
    auto load_kv = [&](int s, int t) {
        const uint32_t base = sb + 32768 + (uint32_t)s * 65536;
        const size_t g = (size_t)(t * 128 + r) * DHEAD;
#pragma unroll
        for (int q = 0; q < 4; q++) {
            const int c = cb + q * 8;
            const uint32_t sw = swz((uint32_t)r * 128u + (uint32_t)c * 2u);
            CP_ASYNC16(base + sw,          Kh + g + c);
            CP_ASYNC16(base + 16384 + sw,  Kl + g + c);
            CP_ASYNC16(base + 32768 + sw,  Vh + g + c);
            CP_ASYNC16(base + 49152 + sw,  Vl + g + c);
        }
        CP_COMMIT();
    };
    load_kv(0, 0);

    // softmax scale folded into exp2: SC = log2(e) / sqrt(T)
    const float SC = 1.4426950408889634f * 0.02209708691207961f;

    uint32_t qh[4][4], ql[4][4];
    float o[8][4];
#pragma unroll
    for (int j = 0; j < 8; j++)
#pragma unroll
        for (int c = 0; c < 4; c++) o[j][c] = 0.f;
    float m0r = -INFINITY, m1r = -INFINITY, l0 = 0.f, l1 = 0.f;

    const int rt0 = wid * 16 + (lane >> 2);   // within-tile row of this thread
    const int lrow = lane & 15;
    const int lkh  = lane >> 4;

#pragma unroll 1
    for (int t = 0; t < ntiles; t++) {
        const int cur = t & 1;
        CP_WAIT0();
        __syncthreads();
        if (t == 0) {
            // preload Q fragments (reused across all KV tiles)
#pragma unroll
            for (int kk = 0; kk < 4; kk++) {
                const uint32_t off = swz((uint32_t)(wid * 16 + lrow) * 128u
                                         + (uint32_t)(kk * 16 + lkh * 8) * 2u);
                LDSM_X4(qh[kk][0], qh[kk][1], qh[kk][2], qh[kk][3], sb + off);
                LDSM_X4(ql[kk][0], ql[kk][1], ql[kk][2], ql[kk][3], sb + 16384 + off);
            }
        }
        if (t + 1 < ntiles) load_kv(cur ^ 1, t + 1);

        const uint32_t st = sb + 32768 + (uint32_t)cur * 65536;

        // ---- S = Q K^T (128 cols per warp) ----
        float s[16][4];
#pragma unroll
        for (int j = 0; j < 16; j++)
#pragma unroll
            for (int c = 0; c < 4; c++) s[j][c] = 0.f;

#pragma unroll
        for (int kk = 0; kk < 4; kk++) {
            const uint32_t kcol = (uint32_t)(kk * 16 + lkh * 8) * 2u;
#pragma unroll
            for (int jj = 0; jj < 8; jj++) {
                const uint32_t off = swz((uint32_t)(jj * 16 + lrow) * 128u + kcol);
                uint32_t kh0, kh1, kh2, kh3, kl0, kl1, kl2, kl3;
                LDSM_X4(kh0, kh1, kh2, kh3, st + off);
                LDSM_X4(kl0, kl1, kl2, kl3, st + 16384 + off);
                MMA16816(s[2*jj],   qh[kk], kh0, kh2);
                MMA16816(s[2*jj],   qh[kk], kl0, kl2);
                MMA16816(s[2*jj],   ql[kk], kh0, kh2);
                MMA16816(s[2*jj+1], qh[kk], kh1, kh3);
                MMA16816(s[2*jj+1], qh[kk], kl1, kl3);
                MMA16816(s[2*jj+1], ql[kk], kh1, kh3);
            }
        }

        // ---- causal mask on the diagonal tile ----
        if (t == ntiles - 1) {
#pragma unroll
            for (int j = 0; j < 16; j++) {
#pragma unroll
                for (int c = 0; c < 2; c++) {
                    const int ct = j * 8 + (lane & 3) * 2 + c;
                    if (ct > rt0)     s[j][c]     = -INFINITY;
                    if (ct > rt0 + 8) s[j][c + 2] = -INFINITY;
                }
            }
        }

        // ---- online softmax (rows rt0, rt0+8) ----
        float mx0 = -INFINITY, mx1 = -INFINITY;
#pragma unroll
        for (int j = 0; j < 16; j++) {
            mx0 = fmaxf(mx0, fmaxf(s[j][0], s[j][1]));
            mx1 = fmaxf(mx1, fmaxf(s[j][2], s[j][3]));
        }
        mx0 = fmaxf(mx0, __shfl_xor_sync(0xffffffffu, mx0, 1));
        mx0 = fmaxf(mx0, __shfl_xor_sync(0xffffffffu, mx0, 2));
        mx1 = fmaxf(mx1, __shfl_xor_sync(0xffffffffu, mx1, 1));
        mx1 = fmaxf(mx1, __shfl_xor_sync(0xffffffffu, mx1, 2));
        const float mn0 = fmaxf(m0r, mx0);
        const float mn1 = fmaxf(m1r, mx1);
        const float c0 = ex2f((m0r - mn0) * SC);
        const float c1 = ex2f((m1r - mn1) * SC);
        m0r = mn0; m1r = mn1;

        float ls0 = 0.f, ls1 = 0.f;
#pragma unroll
        for (int j = 0; j < 16; j++) {
            s[j][0] = ex2f((s[j][0] - mn0) * SC);
            s[j][1] = ex2f((s[j][1] - mn0) * SC);
            s[j][2] = ex2f((s[j][2] - mn1) * SC);
            s[j][3] = ex2f((s[j][3] - mn1) * SC);
            ls0 += s[j][0] + s[j][1];
            ls1 += s[j][2] + s[j][3];
        }
        ls0 += __shfl_xor_sync(0xffffffffu, ls0, 1);
        ls0 += __shfl_xor_sync(0xffffffffu, ls0, 2);
        ls1 += __shfl_xor_sync(0xffffffffu, ls1, 1);
        ls1 += __shfl_xor_sync(0xffffffffu, ls1, 2);
        l0 = l0 * c0 + ls0;
        l1 = l1 * c1 + ls1;
#pragma unroll
        for (int j = 0; j < 8; j++) {
            o[j][0] *= c0; o[j][1] *= c0; o[j][2] *= c1; o[j][3] *= c1;
        }

        // ---- O += P V ----
#pragma unroll
        for (int kk = 0; kk < 8; kk++) {
            uint32_t ahi[4], alo[4];
            split2(s[2*kk][0],   s[2*kk][1],   ahi[0], alo[0]);
            split2(s[2*kk][2],   s[2*kk][3],   ahi[1], alo[1]);
            split2(s[2*kk+1][0], s[2*kk+1][1], ahi[2], alo[2]);
            split2(s[2*kk+1][2], s[2*kk+1][3], ahi[3], alo[3]);
#pragma unroll
            for (int jj = 0; jj < 4; jj++) {
                const uint32_t off = swz((uint32_t)(kk * 16 + lrow) * 128u
                                         + (uint32_t)(jj * 16 + lkh * 8) * 2u);
                uint32_t vh0, vh1, vh2, vh3, vl0, vl1, vl2, vl3;
                LDSM_X4_T(vh0, vh1, vh2, vh3, st + 32768 + off);
                LDSM_X4_T(vl0, vl1, vl2, vl3, st + 49152 + off);
                MMA16816(o[2*jj],   ahi, vh0, vh1);
                MMA16816(o[2*jj],   alo, vh0, vh1);
                MMA16816(o[2*jj],   ahi, vl0, vl1);
                MMA16816(o[2*jj+1], ahi, vh2, vh3);
                MMA16816(o[2*jj+1], alo, vh2, vh3);
                MMA16816(o[2*jj+1], ahi, vl2, vl3);
            }
        }
        __syncthreads();
    }

    // ---- epilogue: normalize, write att as bf16 hi/lo at [b*T+t][h*64+d] ----
    const float inv0 = 1.0f / l0;
    const float inv1 = 1.0f / l1;
    const int colb = h * DHEAD + (lane & 3) * 2;
    const size_t row0 = (size_t)(b * TSEQ + i0 + rt0);
#pragma unroll
    for (int j = 0; j < 8; j++) {
        uint32_t hi, lo;
        const size_t idx0 = row0 * EDIM + colb + j * 8;
        split2(o[j][0] * inv0, o[j][1] * inv0, hi, lo);
        *(uint32_t*)(g_athi + idx0) = hi;
        *(uint32_t*)(g_atlo + idx0) = lo;
        const size_t idx1 = idx0 + (size_t)8 * EDIM;
        split2(o[j][2] * inv1, o[j][3] * inv1, hi, lo);
        *(uint32_t*)(g_athi + idx1) = hi;
        *(uint32_t*)(g_atlo + idx1) = lo;
    }
}

// ---------------------------------------------------------------------------
extern "C" void kernel_launch(void* const* d_in, const int* in_sizes, int n_in,
                              void* d_out, int out_size)
{
    const float* x  = (const float*)d_in[0];
    const float* Wq = (const float*)d_in[2];
    const float* Wk = (const float*)d_in[3];
    const float* Wv = (const float*)d_in[4];
    const float* Wo = (const float*)d_in[5];
    float* out = (float*)d_out;

    cudaFuncSetAttribute(mm128, cudaFuncAttributeMaxDynamicSharedMemorySize, 2 * MMSTAGE);
    cudaFuncSetAttribute(flash_mma, cudaFuncAttributeMaxDynamicSharedMemorySize, FA_SMEM);

    // 1) fp32 -> bf16 hi/lo conversions
    conv_elem<<<(MTOT * EDIM) / (256 * 4), 256>>>(x, 0);
    conv_elem<<<(EDIM * EDIM) / (256 * 4), 256>>>(Wo, 1);
    {
        dim3 g((EDIM * EDIM) / 256, 3);
        conv_w<<<g, 256>>>(Wq, Wk, Wv);
    }

    // 2) QKV projection -> bf16 hi/lo [z][h][m][d]
    {
        dim3 g(EDIM / 128, MTOT / 128, 3);
        mm128<<<g, 256, 2 * MMSTAGE>>>(nullptr, 0);
    }

    // 3) Flash attention (bf16x3 tensor cores)
    {
        dim3 g(TSEQ / 128, NHEAD * BATCH);
        flash_mma<<<g, 256, FA_SMEM>>>();
    }

    // 4) Output projection
    {
        dim3 g(EDIM / 128, MTOT / 128, 1);
        mm128<<<g, 256, 2 * MMSTAGE>>>(out, 1);
    }
}

// round 5
// speedup vs baseline: 2.2574x; 1.0443x over previous
#include <cuda_runtime.h>
#include <cuda_bf16.h>
#include <math.h>
#include <stdint.h>

#define BATCH 2
#define TSEQ  2048
#define EDIM  1024
#define NHEAD 16
#define DHEAD 64
#define MTOT  (BATCH*TSEQ)   // 4096

// ---------------------------------------------------------------------------
// Scratch (static device globals: allocation-free, graph-safe)
// ---------------------------------------------------------------------------
static __device__ __nv_bfloat16  g_xhi[(size_t)MTOT * EDIM];
static __device__ __nv_bfloat16  g_xlo[(size_t)MTOT * EDIM];
static __device__ __nv_bfloat16  g_wthi[(size_t)3 * EDIM * EDIM];   // [z][n=h*64+d][e]
static __device__ __nv_bfloat16  g_wtlo[(size_t)3 * EDIM * EDIM];
static __device__ __nv_bfloat16  g_wohi[(size_t)EDIM * EDIM];       // [n][k]
static __device__ __nv_bfloat16  g_wolo[(size_t)EDIM * EDIM];
static __device__ __nv_bfloat16  g_athi[(size_t)MTOT * EDIM];       // [m][h*64+d]
static __device__ __nv_bfloat16  g_atlo[(size_t)MTOT * EDIM];
// QKV in bf16 hi/lo: [z][h][m=b*T+t][d]
static __device__ __nv_bfloat16  g_pqkvh[(size_t)3 * NHEAD * MTOT * DHEAD];
static __device__ __nv_bfloat16  g_pqkvl[(size_t)3 * NHEAD * MTOT * DHEAD];

// ---------------------------------------------------------------------------
// Portable (sm_100 base) tensor-core helpers
// ---------------------------------------------------------------------------
__device__ __forceinline__ uint32_t smem_u32(const void* p) {
    uint32_t a;
    asm("{ .reg .u64 t; cvta.to.shared.u64 t, %1; cvt.u32.u64 %0, t; }" : "=r"(a) : "l"(p));
    return a;
}
#define CP_ASYNC16(saddr, gptr) \
    asm volatile("cp.async.cg.shared.global [%0], [%1], 16;" :: "r"(saddr), "l"(gptr))
#define CP_COMMIT() asm volatile("cp.async.commit_group;" ::: "memory")
#define CP_WAIT0()  asm volatile("cp.async.wait_group 0;" ::: "memory")

#define LDSM_X4(r0, r1, r2, r3, addr) \
    asm volatile("ldmatrix.sync.aligned.m8n8.x4.shared.b16 {%0,%1,%2,%3}, [%4];" \
                 : "=r"(r0), "=r"(r1), "=r"(r2), "=r"(r3) : "r"(addr))
#define LDSM_X4_T(r0, r1, r2, r3, addr) \
    asm volatile("ldmatrix.sync.aligned.m8n8.x4.trans.shared.b16 {%0,%1,%2,%3}, [%4];" \
                 : "=r"(r0), "=r"(r1), "=r"(r2), "=r"(r3) : "r"(addr))

#define MMA16816(d, a, b0, b1) \
    asm volatile("mma.sync.aligned.m16n8k16.row.col.f32.bf16.bf16.f32 " \
                 "{%0,%1,%2,%3}, {%4,%5,%6,%7}, {%8,%9}, {%0,%1,%2,%3};" \
                 : "+f"((d)[0]), "+f"((d)[1]), "+f"((d)[2]), "+f"((d)[3]) \
                 : "r"((a)[0]), "r"((a)[1]), "r"((a)[2]), "r"((a)[3]), "r"(b0), "r"(b1))

__device__ __forceinline__ uint32_t swz(uint32_t off) {
    return off ^ ((off >> 3) & 0x70);
}
__device__ __forceinline__ float ex2f(float x) {
    float y; asm("ex2.approx.f32 %0, %1;" : "=f"(y) : "f"(x)); return y;
}
__device__ __forceinline__ void split2(float v0, float v1, uint32_t& hi, uint32_t& lo) {
    __nv_bfloat16 h0 = __float2bfloat16(v0), h1 = __float2bfloat16(v1);
    __nv_bfloat162 hp(h0, h1);
    hi = *(const uint32_t*)&hp;
    __nv_bfloat162 lp(__float2bfloat16(v0 - __bfloat162float(h0)),
                      __float2bfloat16(v1 - __bfloat162float(h1)));
    lo = *(const uint32_t*)&lp;
}

// ---------------------------------------------------------------------------
// Conversion kernels: fp32 -> bf16 hi/lo
// ---------------------------------------------------------------------------
__global__ void conv_elem(const float* __restrict__ src, int mode)
{
    __nv_bfloat16* hi = (mode == 0) ? g_xhi : g_wohi;
    __nv_bfloat16* lo = (mode == 0) ? g_xlo : g_wolo;
    const int i4 = blockIdx.x * blockDim.x + threadIdx.x;
    float4 v = *(const float4*)(src + (size_t)i4 * 4);
    uint32_t h0, l0, h1, l1;
    split2(v.x, v.y, h0, l0);
    split2(v.z, v.w, h1, l1);
    *(uint32_t*)(hi + (size_t)i4 * 4)     = h0;
    *(uint32_t*)(hi + (size_t)i4 * 4 + 2) = h1;
    *(uint32_t*)(lo + (size_t)i4 * 4)     = l0;
    *(uint32_t*)(lo + (size_t)i4 * 4 + 2) = l1;
}

__global__ void conv_w(const float* __restrict__ Wq,
                       const float* __restrict__ Wk,
                       const float* __restrict__ Wv)
{
    const int t = blockIdx.x * blockDim.x + threadIdx.x;  // < 1024*1024
    const int n = t >> 10, e = t & 1023;
    const int z = blockIdx.y;
    const float* W = (z == 0) ? Wq : ((z == 1) ? Wk : Wv);
    float v = W[(size_t)(n >> 6) * EDIM * DHEAD + (size_t)e * DHEAD + (n & 63)];
    __nv_bfloat16 h = __float2bfloat16(v);
    g_wthi[(size_t)z * EDIM * EDIM + t] = h;
    g_wtlo[(size_t)z * EDIM * EDIM + t] = __float2bfloat16(v - __bfloat162float(h));
}

// ---------------------------------------------------------------------------
// bf16x3 mma.sync GEMM, 2 CTAs/SM: CTA 128x64, BK=64, 8 warps (4x2),
// warp tile 32x32, 2-stage cp.async, 96KB smem, <=128 regs.
// mode 0: A=x, B=Wt[z], C -> g_pqkvh/l.  mode 1: A=att, B=Wo, C -> out fp32.
// ---------------------------------------------------------------------------
#define MMSTAGE 49152   // Ah 16K | Al 16K | Bh 8K | Bl 8K

__global__ __launch_bounds__(256, 2) void mm64(float* __restrict__ Cout, int mode)
{
    extern __shared__ char smem[];
    const uint32_t sb = smem_u32(smem);
    const int tid = threadIdx.x;
    const int wid = tid >> 5, lane = tid & 31;
    const int z = blockIdx.z;
    const int m0 = blockIdx.y * 128;
    const int n0 = blockIdx.x * 64;

    const __nv_bfloat16* Ah = (mode == 0) ? g_xhi : g_athi;
    const __nv_bfloat16* Al = (mode == 0) ? g_xlo : g_atlo;
    const __nv_bfloat16* Bh = (mode == 0) ? (g_wthi + (size_t)z * EDIM * EDIM) : g_wohi;
    const __nv_bfloat16* Bl = (mode == 0) ? (g_wtlo + (size_t)z * EDIM * EDIM) : g_wolo;

    // A loader: 128 rows, half-row per thread.  B loader: 64 rows, quarter-row.
    const int ra  = tid >> 1;
    const int cba = (tid & 1) * 32;
    const int rb  = tid >> 2;
    const int cbb = (tid & 3) * 16;
    const size_t ga_row = (size_t)(m0 + ra) * EDIM;
    const size_t gb_row = (size_t)(n0 + rb) * EDIM;

    auto load_stage = [&](int s, int k0) {
        const uint32_t base = sb + (uint32_t)s * MMSTAGE;
#pragma unroll
        for (int q = 0; q < 4; q++) {
            const int c = cba + q * 8;
            const uint32_t sw = swz((uint32_t)ra * 128u + (uint32_t)c * 2u);
            CP_ASYNC16(base + sw,          Ah + ga_row + k0 + c);
            CP_ASYNC16(base + 16384 + sw,  Al + ga_row + k0 + c);
        }
#pragma unroll
        for (int q = 0; q < 2; q++) {
            const int c = cbb + q * 8;
            const uint32_t sw = swz((uint32_t)rb * 128u + (uint32_t)c * 2u);
            CP_ASYNC16(base + 32768 + sw,  Bh + gb_row + k0 + c);
            CP_ASYNC16(base + 40960 + sw,  Bl + gb_row + k0 + c);
        }
        CP_COMMIT();
    };

    const int wm = wid >> 1;          // 0..3 -> M offset wm*32
    const int wn = wid & 1;           // 0..1 -> N offset wn*32
    const int lrow = lane & 15;
    const int lkh  = lane >> 4;

    float d[2][4][4];
#pragma unroll
    for (int i = 0; i < 2; i++)
#pragma unroll
        for (int j = 0; j < 4; j++)
#pragma unroll
            for (int c = 0; c < 4; c++) d[i][j][c] = 0.f;

    load_stage(0, 0);

#pragma unroll 1
    for (int kb = 0; kb < 16; kb++) {
        const int cur = kb & 1;
        CP_WAIT0();
        __syncthreads();
        if (kb < 15) load_stage(cur ^ 1, (kb + 1) * 64);

        const uint32_t st = sb + (uint32_t)cur * MMSTAGE;
#pragma unroll
        for (int ks = 0; ks < 4; ks++) {
            const uint32_t kcol = (uint32_t)(ks * 16 + lkh * 8) * 2u;
            uint32_t ah[2][4], al[2][4];
#pragma unroll
            for (int i = 0; i < 2; i++) {
                const uint32_t off = swz((uint32_t)(wm * 32 + i * 16 + lrow) * 128u + kcol);
                LDSM_X4(ah[i][0], ah[i][1], ah[i][2], ah[i][3], st + off);
                LDSM_X4(al[i][0], al[i][1], al[i][2], al[i][3], st + 16384 + off);
            }
            uint32_t bh[2][4], bl[2][4];
#pragma unroll
            for (int j = 0; j < 2; j++) {
                const uint32_t off = swz((uint32_t)(wn * 32 + j * 16 + lrow) * 128u + kcol);
                LDSM_X4(bh[j][0], bh[j][1], bh[j][2], bh[j][3], st + 32768 + off);
                LDSM_X4(bl[j][0], bl[j][1], bl[j][2], bl[j][3], st + 40960 + off);
            }
            // 3 passes of 8 independent MMAs each (hi*hi, hi*lo, lo*hi)
#pragma unroll
            for (int i = 0; i < 2; i++)
#pragma unroll
                for (int j = 0; j < 2; j++) {
                    MMA16816(d[i][2*j],   ah[i], bh[j][0], bh[j][2]);
                    MMA16816(d[i][2*j+1], ah[i], bh[j][1], bh[j][3]);
                }
#pragma unroll
            for (int i = 0; i < 2; i++)
#pragma unroll
                for (int j = 0; j < 2; j++) {
                    MMA16816(d[i][2*j],   ah[i], bl[j][0], bl[j][2]);
                    MMA16816(d[i][2*j+1], ah[i], bl[j][1], bl[j][3]);
                }
#pragma unroll
            for (int i = 0; i < 2; i++)
#pragma unroll
                for (int j = 0; j < 2; j++) {
                    MMA16816(d[i][2*j],   al[i], bh[j][0], bh[j][2]);
                    MMA16816(d[i][2*j+1], al[i], bh[j][1], bh[j][3]);
                }
        }
        __syncthreads();
    }

    const int qrow = lane >> 2, qcol = (lane & 3) * 2;
#pragma unroll
    for (int i = 0; i < 2; i++) {
#pragma unroll
        for (int j = 0; j < 4; j++) {
            const int n = n0 + wn * 32 + j * 8 + qcol;
            const int m1 = m0 + wm * 32 + i * 16 + qrow;
#pragma unroll
            for (int hh = 0; hh < 2; hh++) {
                const int m = m1 + hh * 8;
                const float v0 = d[i][j][hh * 2 + 0];
                const float v1 = d[i][j][hh * 2 + 1];
                if (mode == 0) {
                    const size_t base = (size_t)(n >> 6) * (MTOT * DHEAD)
                                      + (size_t)m * DHEAD + (n & 63);
                    uint32_t hi, lo;
                    split2(v0, v1, hi, lo);
                    *(uint32_t*)(g_pqkvh + (size_t)z * NHEAD * MTOT * DHEAD + base) = hi;
                    *(uint32_t*)(g_pqkvl + (size_t)z * NHEAD * MTOT * DHEAD + base) = lo;
                } else {
                    float* dst = Cout + (size_t)m * EDIM + n;
                    dst[0] = v0; dst[1] = v1;
                }
            }
        }
    }
}

// ---------------------------------------------------------------------------
// Flash attention, 2 CTAs/SM target: 128 q-rows/CTA, KV tiles of 64,
// double-buffered cp.async, 96KB smem, 8 warps, warp tile M=16 x N=64.
// ---------------------------------------------------------------------------
#define FA_SMEM (32768 + 2 * 32768)   // Q hi/lo 32K + 2 KV stages of 32K

__global__ __launch_bounds__(256, 2) void flash_mma()
{
    extern __shared__ char fsm[];
    const uint32_t sb = smem_u32(fsm);
    const int tid = threadIdx.x;
    const int wid = tid >> 5, lane = tid & 31;
    const int h = blockIdx.y >> 1;
    const int b = blockIdx.y & 1;
    const int i0 = (int)(gridDim.x - 1 - blockIdx.x) * 128;  // heavy tiles first
    const int ntiles = i0 / 64 + 2;

    const size_t hb = ((size_t)h * MTOT + (size_t)b * TSEQ) * DHEAD;
    const __nv_bfloat16* Qh = g_pqkvh + hb;
    const __nv_bfloat16* Ql = g_pqkvl + hb;
    const __nv_bfloat16* Kh = g_pqkvh + (size_t)NHEAD * MTOT * DHEAD + hb;
    const __nv_bfloat16* Kl = g_pqkvl + (size_t)NHEAD * MTOT * DHEAD + hb;
    const __nv_bfloat16* Vh = g_pqkvh + (size_t)2 * NHEAD * MTOT * DHEAD + hb;
    const __nv_bfloat16* Vl = g_pqkvl + (size_t)2 * NHEAD * MTOT * DHEAD + hb;

    const int rq  = tid >> 1;
    const int cbq = (tid & 1) * 32;
    const int rk  = tid >> 2;
    const int cbk = (tid & 3) * 16;

    // Q (one-time) + KV stage 0, one commit group
#pragma unroll
    for (int q = 0; q < 4; q++) {
        const int c = cbq + q * 8;
        const uint32_t sw = swz((uint32_t)rq * 128u + (uint32_t)c * 2u);
        CP_ASYNC16(sb + sw,          Qh + (size_t)(i0 + rq) * DHEAD + c);
        CP_ASYNC16(sb + 16384 + sw,  Ql + (size_t)(i0 + rq) * DHEAD + c);
    }
    auto load_kv = [&](int s, int t) {
        const uint32_t base = sb + 32768 + (uint32_t)s * 32768;
        const size_t g = (size_t)(t * 64 + rk) * DHEAD;
#pragma unroll
        for (int q = 0; q < 2; q++) {
            const int c = cbk + q * 8;
            const uint32_t sw = swz((uint32_t)rk * 128u + (uint32_t)c * 2u);
            CP_ASYNC16(base + sw,          Kh + g + c);
            CP_ASYNC16(base + 8192 + sw,   Kl + g + c);
            CP_ASYNC16(base + 16384 + sw,  Vh + g + c);
            CP_ASYNC16(base + 24576 + sw,  Vl + g + c);
        }
        CP_COMMIT();
    };
    load_kv(0, 0);

    const float SC = 1.4426950408889634f * 0.02209708691207961f;  // log2(e)/sqrt(T)

    uint32_t qh[4][4], ql[4][4];
    float o[8][4];
#pragma unroll
    for (int j = 0; j < 8; j++)
#pragma unroll
        for (int c = 0; c < 4; c++) o[j][c] = 0.f;
    float m0r = -INFINITY, m1r = -INFINITY, l0 = 0.f, l1 = 0.f;

    const int rt0 = wid * 16 + (lane >> 2);
    const int lrow = lane & 15;
    const int lkh  = lane >> 4;

#pragma unroll 1
    for (int t = 0; t < ntiles; t++) {
        const int cur = t & 1;
        CP_WAIT0();
        __syncthreads();
        if (t == 0) {
#pragma unroll
            for (int kk = 0; kk < 4; kk++) {
                const uint32_t off = swz((uint32_t)(wid * 16 + lrow) * 128u
                                         + (uint32_t)(kk * 16 + lkh * 8) * 2u);
                LDSM_X4(qh[kk][0], qh[kk][1], qh[kk][2], qh[kk][3], sb + off);
                LDSM_X4(ql[kk][0], ql[kk][1], ql[kk][2], ql[kk][3], sb + 16384 + off);
            }
        }
        if (t + 1 < ntiles) load_kv(cur ^ 1, t + 1);

        const uint32_t st = sb + 32768 + (uint32_t)cur * 32768;

        // ---- S = Q K^T (64 cols per warp) ----
        float s[8][4];
#pragma unroll
        for (int j = 0; j < 8; j++)
#pragma unroll
            for (int c = 0; c < 4; c++) s[j][c] = 0.f;

#pragma unroll
        for (int kk = 0; kk < 4; kk++) {
            const uint32_t kcol = (uint32_t)(kk * 16 + lkh * 8) * 2u;
#pragma unroll
            for (int jj = 0; jj < 4; jj++) {
                const uint32_t off = swz((uint32_t)(jj * 16 + lrow) * 128u + kcol);
                uint32_t kh0, kh1, kh2, kh3, kl0, kl1, kl2, kl3;
                LDSM_X4(kh0, kh1, kh2, kh3, st + off);
                LDSM_X4(kl0, kl1, kl2, kl3, st + 8192 + off);
                MMA16816(s[2*jj],   qh[kk], kh0, kh2);
                MMA16816(s[2*jj+1], qh[kk], kh1, kh3);
                MMA16816(s[2*jj],   qh[kk], kl0, kl2);
                MMA16816(s[2*jj+1], qh[kk], kl1, kl3);
                MMA16816(s[2*jj],   ql[kk], kh0, kh2);
                MMA16816(s[2*jj+1], ql[kk], kh1, kh3);
            }
        }

        // ---- causal mask (only the last two 64-wide tiles can cross the diag) ----
        if (t >= ntiles - 2) {
            const int row0 = i0 + rt0;
#pragma unroll
            for (int j = 0; j < 8; j++) {
#pragma unroll
                for (int c = 0; c < 2; c++) {
                    const int ct = t * 64 + j * 8 + (lane & 3) * 2 + c;
                    if (ct > row0)     s[j][c]     = -INFINITY;
                    if (ct > row0 + 8) s[j][c + 2] = -INFINITY;
                }
            }
        }

        // ---- online softmax ----
        float mx0 = -INFINITY, mx1 = -INFINITY;
#pragma unroll
        for (int j = 0; j < 8; j++) {
            mx0 = fmaxf(mx0, fmaxf(s[j][0], s[j][1]));
            mx1 = fmaxf(mx1, fmaxf(s[j][2], s[j][3]));
        }
        mx0 = fmaxf(mx0, __shfl_xor_sync(0xffffffffu, mx0, 1));
        mx0 = fmaxf(mx0, __shfl_xor_sync(0xffffffffu, mx0, 2));
        mx1 = fmaxf(mx1, __shfl_xor_sync(0xffffffffu, mx1, 1));
        mx1 = fmaxf(mx1, __shfl_xor_sync(0xffffffffu, mx1, 2));
        const float mn0 = fmaxf(m0r, mx0);
        const float mn1 = fmaxf(m1r, mx1);
        const float c0 = ex2f((m0r - mn0) * SC);
        const float c1 = ex2f((m1r - mn1) * SC);
        m0r = mn0; m1r = mn1;

        float ls0 = 0.f, ls1 = 0.f;
#pragma unroll
        for (int j = 0; j < 8; j++) {
            s[j][0] = ex2f((s[j][0] - mn0) * SC);
            s[j][1] = ex2f((s[j][1] - mn0) * SC);
            s[j][2] = ex2f((s[j][2] - mn1) * SC);
            s[j][3] = ex2f((s[j][3] - mn1) * SC);
            ls0 += s[j][0] + s[j][1];
            ls1 += s[j][2] + s[j][3];
        }
        ls0 += __shfl_xor_sync(0xffffffffu, ls0, 1);
        ls0 += __shfl_xor_sync(0xffffffffu, ls0, 2);
        ls1 += __shfl_xor_sync(0xffffffffu, ls1, 1);
        ls1 += __shfl_xor_sync(0xffffffffu, ls1, 2);
        l0 = l0 * c0 + ls0;
        l1 = l1 * c1 + ls1;
#pragma unroll
        for (int j = 0; j < 8; j++) {
            o[j][0] *= c0; o[j][1] *= c0; o[j][2] *= c1; o[j][3] *= c1;
        }

        // ---- O += P V ----
#pragma unroll
        for (int kk = 0; kk < 4; kk++) {
            uint32_t ahi[4], alo[4];
            split2(s[2*kk][0],   s[2*kk][1],   ahi[0], alo[0]);
            split2(s[2*kk][2],   s[2*kk][3],   ahi[1], alo[1]);
            split2(s[2*kk+1][0], s[2*kk+1][1], ahi[2], alo[2]);
            split2(s[2*kk+1][2], s[2*kk+1][3], ahi[3], alo[3]);
#pragma unroll
            for (int jj = 0; jj < 4; jj++) {
                const uint32_t off = swz((uint32_t)(kk * 16 + lrow) * 128u
                                         + (uint32_t)(jj * 16 + lkh * 8) * 2u);
                uint32_t vh0, vh1, vh2, vh3, vl0, vl1, vl2, vl3;
                LDSM_X4_T(vh0, vh1, vh2, vh3, st + 16384 + off);
                LDSM_X4_T(vl0, vl1, vl2, vl3, st + 24576 + off);
                MMA16816(o[2*jj],   ahi, vh0, vh1);
                MMA16816(o[2*jj+1], ahi, vh2, vh3);
                MMA16816(o[2*jj],   alo, vh0, vh1);
                MMA16816(o[2*jj+1], alo, vh2, vh3);
                MMA16816(o[2*jj],   ahi, vl0, vl1);
                MMA16816(o[2*jj+1], ahi, vl2, vl3);
            }
        }
        __syncthreads();
    }

    // ---- epilogue: normalize, write att as bf16 hi/lo at [b*T+t][h*64+d] ----
    const float inv0 = 1.0f / l0;
    const float inv1 = 1.0f / l1;
    const int colb = h * DHEAD + (lane & 3) * 2;
    const size_t row0 = (size_t)(b * TSEQ + i0 + rt0);
#pragma unroll
    for (int j = 0; j < 8; j++) {
        uint32_t hi, lo;
        const size_t idx0 = row0 * EDIM + colb + j * 8;
        split2(o[j][0] * inv0, o[j][1] * inv0, hi, lo);
        *(uint32_t*)(g_athi + idx0) = hi;
        *(uint32_t*)(g_atlo + idx0) = lo;
        const size_t idx1 = idx0 + (size_t)8 * EDIM;
        split2(o[j][2] * inv1, o[j][3] * inv1, hi, lo);
        *(uint32_t*)(g_athi + idx1) = hi;
        *(uint32_t*)(g_atlo + idx1) = lo;
    }
}

// ---------------------------------------------------------------------------
extern "C" void kernel_launch(void* const* d_in, const int* in_sizes, int n_in,
                              void* d_out, int out_size)
{
    const float* x  = (const float*)d_in[0];
    const float* Wq = (const float*)d_in[2];
    const float* Wk = (const float*)d_in[3];
    const float* Wv = (const float*)d_in[4];
    const float* Wo = (const float*)d_in[5];
    float* out = (float*)d_out;

    cudaFuncSetAttribute(mm64, cudaFuncAttributeMaxDynamicSharedMemorySize, 2 * MMSTAGE);
    cudaFuncSetAttribute(flash_mma, cudaFuncAttributeMaxDynamicSharedMemorySize, FA_SMEM);

    // 1) fp32 -> bf16 hi/lo conversions
    conv_elem<<<(MTOT * EDIM) / (256 * 4), 256>>>(x, 0);
    conv_elem<<<(EDIM * EDIM) / (256 * 4), 256>>>(Wo, 1);
    {
        dim3 g((EDIM * EDIM) / 256, 3);
        conv_w<<<g, 256>>>(Wq, Wk, Wv);
    }

    // 2) QKV projection -> bf16 hi/lo [z][h][m][d]
    {
        dim3 g(EDIM / 64, MTOT / 128, 3);
        mm64<<<g, 256, 2 * MMSTAGE>>>(nullptr, 0);
    }

    // 3) Flash attention (bf16x3 tensor cores)
    {
        dim3 g(TSEQ / 128, NHEAD * BATCH);
        flash_mma<<<g, 256, FA_SMEM>>>();
    }

    // 4) Output projection
    {
        dim3 g(EDIM / 64, MTOT / 128, 1);
        mm64<<<g, 256, 2 * MMSTAGE>>>(out, 1);
    }
}